// round 1
// baseline (speedup 1.0000x reference)
#include <cuda_runtime.h>

// ---------------------------------------------------------------------------
// CapsNet forward, fused. Key facts:
//  * routing never updates logits -> c uniform -> s[b,d,i] = mean_n dig[b,n,d]
//  * conv1 channel c = n*8+d; conv2 (kD=1) reduces over n per fixed d
//    -> one block per (b,d) computes conv1(32ch) -> conv2(32x6x6) -> partial
//       contraction with dig_W, with zero recomputation and no HBM intermediate.
//  * fp32 math via packed fma.rn.f32x2 (FFMA2), operands pre-paired in smem.
// ---------------------------------------------------------------------------

typedef unsigned long long ull;

#define NW   6
#define NTHR 192

// smem layout (floats)
#define OFF_X    0        // 784   image
#define OFF_XB   784      // 784   image shifted by +1 col (odd-pair alignment)
#define OFF_W1   1568     // 5184  conv1 weights, duplicated pairs [tap][n]{w,w}
#define OFF_W2   6752     // 5184  conv2 weights, ci-pairs [tap][co]{even,odd}
#define OFF_C1   11936    // 16*812 conv1 output, ci-pair interleaved
#define OFF_RED  24928    // 96    cross-warp reduction
#define SMEM_FLOATS 25024
#define SMEM_BYTES  (SMEM_FLOATS * 4)

__device__ float g_partial[512 * 8 * 16];
__device__ float g_WbSum[16];
__device__ float g_WSum[160];

__device__ __forceinline__ ull ffma2(ull a, ull b, ull c) {
    ull d;
    asm("fma.rn.f32x2 %0, %1, %2, %3;" : "=l"(d) : "l"(a), "l"(b), "l"(c));
    return d;
}
__device__ __forceinline__ float lo32(ull v) { return __uint_as_float((unsigned)(v & 0xffffffffull)); }
__device__ __forceinline__ float hi32(ull v) { return __uint_as_float((unsigned)(v >> 32)); }

// ---------------------------------------------------------------------------
// Kernel 0: tiny per-launch precompute (deterministic every call).
//   g_WbSum[e] = sum_n dig_Wb[n,e]
//   g_WSum[o*16+k] = sum_i out_w[o,i,k]
// ---------------------------------------------------------------------------
__global__ void caps_prep(const float* __restrict__ digWb,
                          const float* __restrict__ outw) {
    __shared__ float acc[256];
    int t = threadIdx.x;
    int e = t & 15, grp = t >> 4;   // 16 groups x 16 e
    float s = 0.f;
    for (int n = grp; n < 1152; n += 16) s += digWb[n * 16 + e];
    acc[t] = s;
    __syncthreads();
    if (t < 16) {
        float tot = 0.f;
        #pragma unroll
        for (int g = 0; g < 16; g++) tot += acc[g * 16 + t];
        g_WbSum[t] = tot;
    }
    if (t < 160) {
        int o = t / 16, k = t & 15;
        float w = 0.f;
        #pragma unroll
        for (int i = 0; i < 10; i++) w += outw[(o * 10 + i) * 16 + k];
        g_WSum[t] = w;
    }
}

// ---------------------------------------------------------------------------
// Kernel 1: fused conv1 + relu + conv2(stride2) + relu + dig_W partial
// grid (8 d-slices, 512 batches), 192 threads (6 warps; lane = channel).
// ---------------------------------------------------------------------------
__global__ void __launch_bounds__(NTHR, 2)
caps_fused(const float* __restrict__ gx,  const float* __restrict__ gw1,
           const float* __restrict__ gb1, const float* __restrict__ gw2,
           const float* __restrict__ gpb, const float* __restrict__ gdW)
{
    extern __shared__ float sm[];
    float* X   = sm + OFF_X;
    float* XB  = sm + OFF_XB;
    float* W1  = sm + OFF_W1;
    float* W2  = sm + OFF_W2;
    float* C1  = sm + OFF_C1;
    float* RED = sm + OFF_RED;

    const int d    = blockIdx.x;      // 0..7
    const int b    = blockIdx.y;      // 0..511
    const int tid  = threadIdx.x;
    const int lane = tid & 31;
    const int warp = tid >> 5;        // 0..5

    // ---- stage smem: image (+1-shifted copy) and conv1 weights -----------
    for (int i = tid; i < 784; i += NTHR) X[i] = gx[b * 784 + i];
    for (int i = tid; i < 784; i += NTHR) {
        int c = i % 28;
        XB[i] = (c < 27) ? gx[b * 784 + i + 1] : 0.f;
    }
    for (int i = tid; i < 2592; i += NTHR) {
        int n = i / 81, tap = i % 81;
        float w = gw1[(n * 8 + d) * 81 + tap];
        W1[(tap * 32 + n) * 2 + 0] = w;
        W1[(tap * 32 + n) * 2 + 1] = w;
    }
    __syncthreads();

    const float b1 = gb1[lane * 8 + d];

    // ---- conv1: 9x9 VALID, 28x28 -> 20x20, channel = lane -----------------
    // output stored in ci-pair interleaved layout:
    //   C1[(ci>>1)*812 + pixel*2 + (ci&1)]
    for (int y = warp; y < 20; y += NW) {
        ull accP[10];
        #pragma unroll
        for (int xp = 0; xp < 10; xp++) accP[xp] = 0ull;

        #pragma unroll 1
        for (int ky = 0; ky < 9; ky++) {
            const float* row  = X  + (y + ky) * 28;
            const float* rowB = XB + (y + ky) * 28;
            ull P[27];
            #pragma unroll
            for (int j = 0; j < 27; j++)
                P[j] = (j & 1) ? *(const ull*)(rowB + (j - 1))
                               : *(const ull*)(row + j);
            #pragma unroll
            for (int kx = 0; kx < 9; kx++) {
                ull wp = *(const ull*)(W1 + ((ky * 9 + kx) * 32 + lane) * 2);
                #pragma unroll
                for (int xp = 0; xp < 10; xp++)
                    accP[xp] = ffma2(P[2 * xp + kx], wp, accP[xp]);
            }
        }
        const int cbase = (lane >> 1) * 812 + (lane & 1);
        #pragma unroll
        for (int xp = 0; xp < 10; xp++) {
            float v0 = fmaxf(lo32(accP[xp]) + b1, 0.f);
            float v1 = fmaxf(hi32(accP[xp]) + b1, 0.f);
            C1[cbase + (y * 20 + 2 * xp) * 2]     = v0;
            C1[cbase + (y * 20 + 2 * xp + 1) * 2] = v1;
        }
    }

    // ---- conv2: 32ci -> 32co, 9x9 stride 2, 20x20 -> 6x6 ------------------
    // lane = co, warp = output row y; acc halves hold even/odd-ci sums.
    const float pb = gpb[lane];
    ull acc2[6];
    #pragma unroll
    for (int x = 0; x < 6; x++) acc2[x] = 0ull;

    #pragma unroll 1
    for (int ci2 = 0; ci2 < 16; ci2++) {
        __syncthreads();   // previous W2 consumers done
        for (int i = tid; i < 2592; i += NTHR) {
            int co = i / 81, tap = i % 81;
            float wa = gw2[co * 2592 + (2 * ci2)     * 81 + tap];
            float wb = gw2[co * 2592 + (2 * ci2 + 1) * 81 + tap];
            W2[(tap * 32 + co) * 2 + 0] = wa;
            W2[(tap * 32 + co) * 2 + 1] = wb;
        }
        __syncthreads();

        const float* cb = C1 + ci2 * 812;
        #pragma unroll 1
        for (int ky = 0; ky < 9; ky++) {
            const float* rp = cb + (2 * warp + ky) * 40;
            ull P[20];
            #pragma unroll
            for (int c4 = 0; c4 < 10; c4++) {
                ulonglong2 q = *(const ulonglong2*)(rp + c4 * 4); // 2 ci-pairs
                P[2 * c4]     = q.x;
                P[2 * c4 + 1] = q.y;
            }
            #pragma unroll
            for (int kx = 0; kx < 9; kx++) {
                ull wp = *(const ull*)(W2 + ((ky * 9 + kx) * 32 + lane) * 2);
                #pragma unroll
                for (int x = 0; x < 6; x++)
                    acc2[x] = ffma2(P[2 * x + kx], wp, acc2[x]);
            }
        }
    }

    // ---- bias+relu -> u[n,d]; partial contraction with dig_W --------------
    // n = co*36 + x*6 + y  (from swapaxes(2,4).reshape)
    float u[6];
    #pragma unroll
    for (int x = 0; x < 6; x++)
        u[x] = fmaxf(lo32(acc2[x]) + hi32(acc2[x]) + pb, 0.f);

    float part[16];
    #pragma unroll
    for (int e = 0; e < 16; e++) part[e] = 0.f;
    #pragma unroll
    for (int x = 0; x < 6; x++) {
        int n = lane * 36 + x * 6 + warp;
        const float4* wv = reinterpret_cast<const float4*>(gdW + n * 128 + d * 16);
        #pragma unroll
        for (int q = 0; q < 4; q++) {
            float4 w4 = wv[q];
            part[q * 4 + 0] += u[x] * w4.x;
            part[q * 4 + 1] += u[x] * w4.y;
            part[q * 4 + 2] += u[x] * w4.z;
            part[q * 4 + 3] += u[x] * w4.w;
        }
    }
    #pragma unroll
    for (int off = 16; off; off >>= 1) {
        #pragma unroll
        for (int e = 0; e < 16; e++)
            part[e] += __shfl_xor_sync(0xffffffffu, part[e], off);
    }
    if (lane == 0) {
        #pragma unroll
        for (int e = 0; e < 16; e++) RED[warp * 16 + e] = part[e];
    }
    __syncthreads();
    if (tid < 16) {
        float s = 0.f;
        #pragma unroll
        for (int w = 0; w < NW; w++) s += RED[w * 16 + tid];
        g_partial[(b * 8 + d) * 16 + tid] = s;
    }
}

// ---------------------------------------------------------------------------
// Kernel 2: squash + output conv + softmax. One warp per batch.
// ---------------------------------------------------------------------------
__global__ void caps_final(const float* __restrict__ outb, float* __restrict__ out) {
    const int b = blockIdx.x;
    const int lane = threadIdx.x;

    float sb = 0.f;
    if (lane < 16) {
        float s = g_WbSum[lane];
        #pragma unroll
        for (int d = 0; d < 8; d++) s += g_partial[(b * 8 + d) * 16 + lane];
        sb = s * (1.0f / 1152.0f);
    }
    float sq = sb * sb, ab = fabsf(sb);
    #pragma unroll
    for (int off = 16; off; off >>= 1) {
        sq += __shfl_xor_sync(0xffffffffu, sq, off);
        ab += __shfl_xor_sync(0xffffffffu, ab, off);
    }
    float l2 = sqrtf(sq);
    float scale = l2 / ((1.f + l2) * ab);

    __shared__ float vsh[16];
    if (lane < 16) vsh[lane] = sb * scale;
    __syncwarp();

    float logit = -INFINITY;
    if (lane < 10) {
        float L = outb[lane];
        #pragma unroll
        for (int e = 0; e < 16; e++) L += vsh[e] * g_WSum[lane * 16 + e];
        logit = L;
    }
    float m = logit;
    #pragma unroll
    for (int off = 16; off; off >>= 1)
        m = fmaxf(m, __shfl_xor_sync(0xffffffffu, m, off));
    float ex = (lane < 10) ? expf(logit - m) : 0.f;
    float s = ex;
    #pragma unroll
    for (int off = 16; off; off >>= 1)
        s += __shfl_xor_sync(0xffffffffu, s, off);
    if (lane < 10) out[b * 10 + lane] = ex / s;
}

// ---------------------------------------------------------------------------
extern "C" void kernel_launch(void* const* d_in, const int* in_sizes, int n_in,
                              void* d_out, int out_size) {
    const float* x   = (const float*)d_in[0];   // [512,1,28,28]
    const float* w1  = (const float*)d_in[1];   // [256,1,9,9]
    const float* b1  = (const float*)d_in[2];   // [256]
    const float* w2  = (const float*)d_in[3];   // [32,32,1,9,9]
    const float* pb  = (const float*)d_in[4];   // [32]
    const float* dW  = (const float*)d_in[5];   // [1152,8,16]
    const float* dWb = (const float*)d_in[6];   // [1152,16]
    const float* ow  = (const float*)d_in[7];   // [10,10,16,1]
    const float* ob  = (const float*)d_in[8];   // [10]
    float* out = (float*)d_out;                 // [512,10]

    (void)cudaFuncSetAttribute(caps_fused,
                               cudaFuncAttributeMaxDynamicSharedMemorySize,
                               SMEM_BYTES);

    caps_prep<<<1, 256>>>(dWb, ow);
    caps_fused<<<dim3(8, 512), NTHR, SMEM_BYTES>>>(x, w1, b1, w2, pb, dW);
    caps_final<<<512, 32>>>(ob, out);
}

// round 2
// speedup vs baseline: 1.4510x; 1.4510x over previous
#include <cuda_runtime.h>

// ---------------------------------------------------------------------------
// CapsNet forward, fused.
//  * routing never updates logits -> c uniform -> s[b,d,i] = mean_n dig[b,n,d]
//  * conv1 channel c = n*8+d; conv2 (kD=1) reduces over n per fixed d
//    -> one block per (b,d): conv1(32ch) -> conv2(32x6x6) -> dig_W partial.
//  * fp32 via packed fma.rn.f32x2; weights pre-paired in gmem by prep kernel;
//    75.3 KB smem -> 3 blocks/SM (18 warps) for latency hiding.
// ---------------------------------------------------------------------------

typedef unsigned long long ull;

#define NW   6
#define NTHR 192

// smem layout (floats)
#define OFF_X    0          // 784  image (reused as RED after conv1)
#define OFF_W    784        // 5184 W1 (conv1 phase) then W2 (per-ci2)
#define OFF_C1   5968       // 16 * 804, ci-pair interleaved conv1 output
#define C1_STRIDE 804
#define SMEM_FLOATS (5968 + 16 * 804)   // 18832 -> 75.3 KB
#define SMEM_BYTES  (SMEM_FLOATS * 4)

__device__ float g_W1p[8][5184];    // [d][(tap*32+n)*2 + {0,1}] duplicated pair
__device__ float g_W2p[16][5184];   // [ci2][(tap*32+co)*2 + {even,odd}]
__device__ float g_partial[512 * 8 * 16];
__device__ float g_WbSum[16];
__device__ float g_WSum[160];

__device__ __forceinline__ ull ffma2(ull a, ull b, ull c) {
    ull d;
    asm("fma.rn.f32x2 %0, %1, %2, %3;" : "=l"(d) : "l"(a), "l"(b), "l"(c));
    return d;
}
__device__ __forceinline__ float lo32(ull v) { return __uint_as_float((unsigned)v); }
__device__ __forceinline__ float hi32(ull v) { return __uint_as_float((unsigned)(v >> 32)); }
__device__ __forceinline__ ull packf(unsigned lo, unsigned hi) {
    return ((ull)hi << 32) | lo;
}

// ---------------------------------------------------------------------------
// prepW: pre-pair conv weights into the smem-friendly layout (runs each call).
// ---------------------------------------------------------------------------
__global__ void caps_prepW(const float* __restrict__ w1,
                           const float* __restrict__ w2) {
    int t = blockIdx.x * blockDim.x + threadIdx.x;
    if (t < 8 * 2592) {
        int d = t / 2592, i = t % 2592;
        int n = i / 81, tap = i % 81;
        float w = w1[(n * 8 + d) * 81 + tap];
        g_W1p[d][(tap * 32 + n) * 2 + 0] = w;
        g_W1p[d][(tap * 32 + n) * 2 + 1] = w;
    }
    if (t < 16 * 2592) {
        int c2 = t / 2592, i = t % 2592;
        int co = i / 81, tap = i % 81;
        g_W2p[c2][(tap * 32 + co) * 2 + 0] = w2[co * 2592 + (2 * c2) * 81 + tap];
        g_W2p[c2][(tap * 32 + co) * 2 + 1] = w2[co * 2592 + (2 * c2 + 1) * 81 + tap];
    }
}

// ---------------------------------------------------------------------------
// prepS: sums needed only by the final kernel.
// ---------------------------------------------------------------------------
__global__ void caps_prepS(const float* __restrict__ digWb,
                           const float* __restrict__ outw) {
    __shared__ float acc[256];
    int t = threadIdx.x;
    int e = t & 15, grp = t >> 4;
    float s = 0.f;
    for (int n = grp; n < 1152; n += 16) s += digWb[n * 16 + e];
    acc[t] = s;
    __syncthreads();
    if (t < 16) {
        float tot = 0.f;
        #pragma unroll
        for (int g = 0; g < 16; g++) tot += acc[g * 16 + t];
        g_WbSum[t] = tot;
    }
    if (t < 160) {
        int o = t / 16, k = t & 15;
        float w = 0.f;
        #pragma unroll
        for (int i = 0; i < 10; i++) w += outw[(o * 10 + i) * 16 + k];
        g_WSum[t] = w;
    }
}

// ---------------------------------------------------------------------------
// fused conv1 + relu + conv2(stride2) + relu + dig_W partial
// grid (8 d, 512 b), 192 threads (6 warps; lane = channel).
// ---------------------------------------------------------------------------
__global__ void __launch_bounds__(NTHR, 3)
caps_fused(const float* __restrict__ gx,  const float* __restrict__ gb1,
           const float* __restrict__ gpb, const float* __restrict__ gdW)
{
    extern __shared__ float sm[];
    float* X   = sm + OFF_X;
    float* Wsh = sm + OFF_W;
    float* C1  = sm + OFF_C1;
    float* RED = sm + OFF_X;     // overlaps X (dead after conv1)

    const int d    = blockIdx.x;
    const int b    = blockIdx.y;
    const int tid  = threadIdx.x;
    const int lane = tid & 31;
    const int warp = tid >> 5;

    // ---- stage image + W1 (vectorized) ------------------------------------
    {
        const float4* xs = reinterpret_cast<const float4*>(gx + b * 784);
        float4* xd = reinterpret_cast<float4*>(X);
        for (int i = tid; i < 196; i += NTHR) xd[i] = xs[i];
        const float4* ws = reinterpret_cast<const float4*>(g_W1p[d]);
        float4* wd = reinterpret_cast<float4*>(Wsh);
        for (int i = tid; i < 1296; i += NTHR) wd[i] = ws[i];
    }
    __syncthreads();

    const float b1 = gb1[lane * 8 + d];

    // ---- conv1: 9x9 VALID, 28x28 -> 20x20, channel = lane ------------------
    // output: C1[(ci>>1)*C1_STRIDE + pixel*2 + (ci&1)]
    for (int y = warp; y < 20; y += NW) {
        ull accP[10];
        #pragma unroll
        for (int xp = 0; xp < 10; xp++) accP[xp] = 0ull;

        #pragma unroll 1
        for (int ky = 0; ky < 9; ky++) {
            const float* row = X + (y + ky) * 28;
            ull P[27];
            #pragma unroll
            for (int i = 0; i < 14; i++) P[2 * i] = *(const ull*)(row + 2 * i);
            #pragma unroll
            for (int i = 0; i < 13; i++)
                P[2 * i + 1] = packf((unsigned)(P[2 * i] >> 32),
                                     (unsigned)P[2 * i + 2]);
            #pragma unroll
            for (int kx = 0; kx < 9; kx++) {
                ull wp = *(const ull*)(Wsh + ((ky * 9 + kx) * 32 + lane) * 2);
                #pragma unroll
                for (int xp = 0; xp < 10; xp++)
                    accP[xp] = ffma2(P[2 * xp + kx], wp, accP[xp]);
            }
        }
        const int cbase = (lane >> 1) * C1_STRIDE + (lane & 1);
        #pragma unroll
        for (int xp = 0; xp < 10; xp++) {
            float v0 = fmaxf(lo32(accP[xp]) + b1, 0.f);
            float v1 = fmaxf(hi32(accP[xp]) + b1, 0.f);
            C1[cbase + (y * 20 + 2 * xp) * 2]     = v0;
            C1[cbase + (y * 20 + 2 * xp + 1) * 2] = v1;
        }
    }

    // ---- conv2: 32ci -> 32co, 9x9 stride 2, 20x20 -> 6x6 -------------------
    const float pb = gpb[lane];
    ull acc2[6];
    #pragma unroll
    for (int x = 0; x < 6; x++) acc2[x] = 0ull;

    #pragma unroll 1
    for (int ci2 = 0; ci2 < 16; ci2++) {
        __syncthreads();   // previous Wsh consumers done (also fences conv1)
        {
            const float4* ws = reinterpret_cast<const float4*>(g_W2p[ci2]);
            float4* wd = reinterpret_cast<float4*>(Wsh);
            for (int i = tid; i < 1296; i += NTHR) wd[i] = ws[i];
        }
        __syncthreads();

        const float* cb = C1 + ci2 * C1_STRIDE;
        #pragma unroll 1
        for (int ky = 0; ky < 9; ky++) {
            const float* rp = cb + (2 * warp + ky) * 40;
            ull P[20];
            #pragma unroll
            for (int c4 = 0; c4 < 10; c4++) {
                ulonglong2 q = *(const ulonglong2*)(rp + c4 * 4);
                P[2 * c4]     = q.x;
                P[2 * c4 + 1] = q.y;
            }
            #pragma unroll
            for (int kx = 0; kx < 9; kx++) {
                ull wp = *(const ull*)(Wsh + ((ky * 9 + kx) * 32 + lane) * 2);
                #pragma unroll
                for (int x = 0; x < 6; x++)
                    acc2[x] = ffma2(P[2 * x + kx], wp, acc2[x]);
            }
        }
    }

    // ---- bias+relu -> u; partial contraction with dig_W --------------------
    float u[6];
    #pragma unroll
    for (int x = 0; x < 6; x++)
        u[x] = fmaxf(lo32(acc2[x]) + hi32(acc2[x]) + pb, 0.f);

    float part[16];
    #pragma unroll
    for (int e = 0; e < 16; e++) part[e] = 0.f;
    #pragma unroll
    for (int x = 0; x < 6; x++) {
        int n = lane * 36 + x * 6 + warp;
        const float4* wv = reinterpret_cast<const float4*>(gdW + n * 128 + d * 16);
        #pragma unroll
        for (int q = 0; q < 4; q++) {
            float4 w4 = wv[q];
            part[q * 4 + 0] += u[x] * w4.x;
            part[q * 4 + 1] += u[x] * w4.y;
            part[q * 4 + 2] += u[x] * w4.z;
            part[q * 4 + 3] += u[x] * w4.w;
        }
    }
    #pragma unroll
    for (int off = 16; off; off >>= 1) {
        #pragma unroll
        for (int e = 0; e < 16; e++)
            part[e] += __shfl_xor_sync(0xffffffffu, part[e], off);
    }
    __syncthreads();   // C1/X consumers done; RED (=X) safe to write
    if (lane == 0) {
        #pragma unroll
        for (int e = 0; e < 16; e++) RED[warp * 16 + e] = part[e];
    }
    __syncthreads();
    if (tid < 16) {
        float s = 0.f;
        #pragma unroll
        for (int w = 0; w < NW; w++) s += RED[w * 16 + tid];
        g_partial[(b * 8 + d) * 16 + tid] = s;
    }
}

// ---------------------------------------------------------------------------
// final: squash + output conv + softmax. One warp per batch.
// ---------------------------------------------------------------------------
__global__ void caps_final(const float* __restrict__ outb, float* __restrict__ out) {
    const int b = blockIdx.x;
    const int lane = threadIdx.x;

    float sb = 0.f;
    if (lane < 16) {
        float s = g_WbSum[lane];
        #pragma unroll
        for (int d = 0; d < 8; d++) s += g_partial[(b * 8 + d) * 16 + lane];
        sb = s * (1.0f / 1152.0f);
    }
    float sq = sb * sb, ab = fabsf(sb);
    #pragma unroll
    for (int off = 16; off; off >>= 1) {
        sq += __shfl_xor_sync(0xffffffffu, sq, off);
        ab += __shfl_xor_sync(0xffffffffu, ab, off);
    }
    float l2 = sqrtf(sq);
    float scale = l2 / ((1.f + l2) * ab);

    __shared__ float vsh[16];
    if (lane < 16) vsh[lane] = sb * scale;
    __syncwarp();

    float logit = -INFINITY;
    if (lane < 10) {
        float L = outb[lane];
        #pragma unroll
        for (int e = 0; e < 16; e++) L += vsh[e] * g_WSum[lane * 16 + e];
        logit = L;
    }
    float m = logit;
    #pragma unroll
    for (int off = 16; off; off >>= 1)
        m = fmaxf(m, __shfl_xor_sync(0xffffffffu, m, off));
    float ex = (lane < 10) ? expf(logit - m) : 0.f;
    float s = ex;
    #pragma unroll
    for (int off = 16; off; off >>= 1)
        s += __shfl_xor_sync(0xffffffffu, s, off);
    if (lane < 10) out[b * 10 + lane] = ex / s;
}

// ---------------------------------------------------------------------------
extern "C" void kernel_launch(void* const* d_in, const int* in_sizes, int n_in,
                              void* d_out, int out_size) {
    const float* x   = (const float*)d_in[0];   // [512,1,28,28]
    const float* w1  = (const float*)d_in[1];   // [256,1,9,9]
    const float* b1  = (const float*)d_in[2];   // [256]
    const float* w2  = (const float*)d_in[3];   // [32,32,1,9,9]
    const float* pb  = (const float*)d_in[4];   // [32]
    const float* dW  = (const float*)d_in[5];   // [1152,8,16]
    const float* dWb = (const float*)d_in[6];   // [1152,16]
    const float* ow  = (const float*)d_in[7];   // [10,10,16,1]
    const float* ob  = (const float*)d_in[8];   // [10]
    float* out = (float*)d_out;                 // [512,10]

    (void)cudaFuncSetAttribute(caps_fused,
                               cudaFuncAttributeMaxDynamicSharedMemorySize,
                               SMEM_BYTES);

    caps_prepW<<<162, 256>>>(w1, w2);
    caps_fused<<<dim3(8, 512), NTHR, SMEM_BYTES>>>(x, b1, pb, dW);
    caps_prepS<<<1, 256>>>(dWb, ow);
    caps_final<<<512, 32>>>(ob, out);
}